// round 3
// baseline (speedup 1.0000x reference)
#include <cuda_runtime.h>
#include <cuda_bf16.h>
#include <cstdint>

#define TT 15
#define C1 6
#define F1 30
#define H1 252
#define HPADIN 256
#define HP 126
#define HPD 128
#define F2 250
#define NPIX (HP*HP)          /* 15876 */
#define TAPS 270
#define POT_OFF 59535000u
#define WIN_OFF 119070000u

// ---------------- device scratch (static, no runtime allocation) ----------------
__device__ uint8_t  g_cs[TT*HPADIN*HPADIN];          // padded per-pixel channel sums (0..6)
__device__ uint32_t g_bits[TT*C1*HPADIN*8];          // packed binary input rows (padded coords)
__device__ uint8_t  g_pool[TT*F1*HPD*HPD];           // pooled+padded spikes
__device__ uint8_t  g_pc[TT*HPD*HPD];                // pooled per-pixel channel count (0..30)
__device__ float    g_w2t[TAPS*256];                 // w2 transposed, feature padded to 256
__device__ float    g_S[256];                        // per-feature full-window sum
__device__ float    g_minwf[F1], g_maxwf[F1];
__device__ float    g_minwA, g_maxwA;
__device__ int      g_allpos;
__device__ float    g_iMaxv;                         // interior (all-full) max/argmax
__device__ int      g_iMaxi;
__device__ float    g_maxv[TT*NPIX];
__device__ int      g_maxi[TT*NPIX];
__device__ float    g_pv[TT*NPIX];                   // pot value of winning channel per (t,pix)
__device__ int      g_win[NPIX];
__device__ uint8_t  g_fired[NPIX];
__device__ float    g_val[NPIX];
__device__ float    g_total[NPIX];
__device__ int      g_list[TT*NPIX];
__device__ int      g_count;
__device__ int      g_vmaxbits;

// ---------------- K: reset scratch ----------------
__global__ void k_zero() {
    int i = blockIdx.x * 256 + threadIdx.x;
    const int NP4 = (int)(sizeof(g_pool) / 16);   // 460800
    const int NC4 = (int)(sizeof(g_pc) / 16);     // 15360
    if (i < NP4) ((int4*)g_pool)[i] = make_int4(0, 0, 0, 0);
    if (i < NC4) ((int4*)g_pc)[i]   = make_int4(0, 0, 0, 0);
    if (i == 0) { g_count = 0; g_vmaxbits = 0; }
}

// ---------------- K: w1 min/max per feature + global ----------------
__global__ void k_wprep(const float* __restrict__ w1) {
    __shared__ float smn[32], smx[32];
    int f = threadIdx.x;
    if (f < F1) {
        float mn = 1e30f, mx = -1e30f;
        for (int i = 0; i < 150; i++) {
            float w = w1[f * 150 + i];
            mn = fminf(mn, w); mx = fmaxf(mx, w);
        }
        g_minwf[f] = mn; g_maxwf[f] = mx;
        smn[f] = mn; smx[f] = mx;
    }
    __syncthreads();
    if (f == 0) {
        float mn = 1e30f, mx = -1e30f;
        for (int i = 0; i < F1; i++) { mn = fminf(mn, smn[i]); mx = fmaxf(mx, smx[i]); }
        g_minwA = mn; g_maxwA = mx; g_allpos = (mn > 0.f) ? 1 : 0;
    }
}

// ---------------- K: transpose w2 ----------------
__global__ void k_w2t(const float* __restrict__ w2) {
    int tap = blockIdx.x;       // 0..269  (= c*9 + p)
    int f = threadIdx.x;        // 0..255
    g_w2t[tap * 256 + f] = (f < F2) ? w2[f * TAPS + tap] : 0.0f;
}

// ---------------- K: per-feature full-window sums + interior argmax ----------------
__global__ void k_prep(const float* __restrict__ w2) {
    __shared__ float sS[256];
    int f = threadIdx.x;
    float s = 0.f;
    if (f < F2) for (int t = 0; t < TAPS; t++) s += w2[f * TAPS + t];
    g_S[f] = (f < F2) ? s : 0.f;
    float sf = (f < F2 && s > 10.f) ? s : 0.f;
    sS[f] = sf;
    __syncthreads();
    if (f == 0) {
        float mv = sS[0]; int mi = 0;
        for (int i = 1; i < F2; i++) if (sS[i] > mv) { mv = sS[i]; mi = i; }
        g_iMaxv = mv; g_iMaxi = mi;
    }
}

// ---------------- K A1: padded channel sums + packed bits ----------------
__global__ void kA1(const int* __restrict__ inp) {
    int bid = blockIdx.x;
    int t = bid >> 8, py = bid & 255;
    int px = threadIdx.x;               // 0..255, full row
    int iy = py - 2, ix = px - 2;
    bool inr = (iy >= 0 && iy < H1 && ix >= 0 && ix < H1);
    int sum = 0;
    int bits[C1];
#pragma unroll
    for (int c = 0; c < C1; c++) {
        int v = inr ? inp[(((t * C1 + c) * H1) + iy) * H1 + ix] : 0;
        bits[c] = v; sum += v;
    }
    g_cs[(t * HPADIN + py) * HPADIN + px] = (uint8_t)sum;
#pragma unroll
    for (int c = 0; c < C1; c++) {
        unsigned m = __ballot_sync(0xFFFFFFFFu, bits[c]);
        if ((px & 31) == 0)
            g_bits[((t * C1 + c) * HPADIN + py) * 8 + (px >> 5)] = m;
    }
}

// ---------------- K A2: conv1 firing bits (count-bound trick) + maxpool + channel count ----------------
__global__ void __launch_bounds__(128) kA2(const float* __restrict__ w1) {
    __shared__ uint8_t  scs[12][72];
    __shared__ uint32_t sb[C1][12][4];
    __shared__ float    sminf[F1], smaxf[F1];
    int t = blockIdx.z;
    int px0 = blockIdx.x * 32, py0 = blockIdx.y * 4;
    int cx0 = px0 * 2, cy0 = py0 * 2;
    int tid = threadIdx.y * 32 + threadIdx.x;

    for (int i = tid; i < 12 * 72; i += 128) {
        int r = i / 72, cc = i % 72;
        int gr = cy0 + r, gc = cx0 + cc;
        uint8_t v = 0;
        if (gr < HPADIN && gc < HPADIN && cc < 68) v = g_cs[(t * HPADIN + gr) * HPADIN + gc];
        scs[r][cc] = v;
    }
    int wb = cx0 >> 5;
    for (int i = tid; i < C1 * 12 * 4; i += 128) {
        int c = i / 48, r = (i / 4) % 12, w = i & 3;
        int gr = cy0 + r, gw = wb + w;
        uint32_t v = 0;
        if (gr < HPADIN && gw < 8) v = g_bits[((t * C1 + c) * HPADIN + gr) * 8 + gw];
        sb[c][r][w] = v;
    }
    if (tid < F1) { sminf[tid] = g_minwf[tid]; smaxf[tid] = g_maxwf[tid]; }
    __syncthreads();

    int px = px0 + threadIdx.x, py = py0 + threadIdx.y;
    if (px >= HP || py >= HP) return;
    int lr = 2 * threadIdx.y, lc = 2 * threadIdx.x;

    int cnt[2][2];
#pragma unroll
    for (int dy = 0; dy < 2; dy++)
#pragma unroll
        for (int dx = 0; dx < 2; dx++) {
            int s = 0;
#pragma unroll
            for (int i = 0; i < 5; i++)
#pragma unroll
                for (int j = 0; j < 5; j++)
                    s += scs[lr + dy + i][lc + dx + j];
            cnt[dy][dx] = s;
        }

    bool ap = (g_allpos != 0);
    float mnA = g_minwA, mxA = g_maxwA;
    uint8_t* poolbase = &g_pool[((size_t)t * F1) * HPD * HPD + (size_t)(py + 1) * HPD + (px + 1)];

    bool allf = ap, allz = ap;
#pragma unroll
    for (int dy = 0; dy < 2; dy++)
#pragma unroll
        for (int dx = 0; dx < 2; dx++) {
            allf = allf && (mnA * cnt[dy][dx] > 15.001f);
            allz = allz && (mxA * cnt[dy][dx] < 14.999f);
        }
    if (allf) {
#pragma unroll
        for (int c = 0; c < F1; c++) poolbase[(size_t)c * HPD * HPD] = 1;
        g_pc[(t * HPD + py + 1) * HPD + px + 1] = F1;
        return;
    }
    if (allz) return;  // pool/pc pre-zeroed

    int pcv = 0;
    for (int f = 0; f < F1; f++) {
        float mn = sminf[f], mx = smaxf[f];
        int pooled = 0;
        for (int dy = 0; dy < 2 && !pooled; dy++)
            for (int dx = 0; dx < 2 && !pooled; dx++) {
                int c = cnt[dy][dx];
                int fire;
                if (ap && mn * c > 15.001f) fire = 1;
                else if (ap && mx * c < 14.999f) fire = 0;
                else {
                    // exact 5x5x6 dot product from packed bits
                    float pot = 0.f;
                    int off = lc + dx;
                    int w = off >> 5, s = off & 31;
                    for (int ch = 0; ch < C1; ch++) {
#pragma unroll
                        for (int i = 0; i < 5; i++) {
                            uint32_t lo = sb[ch][lr + dy + i][w];
                            uint32_t hi = sb[ch][lr + dy + i][w + 1];
                            uint32_t ck = __funnelshift_r(lo, hi, s);
                            const float* wp = &w1[((f * C1 + ch) * 5 + i) * 5];
#pragma unroll
                            for (int j = 0; j < 5; j++)
                                if ((ck >> j) & 1) pot += __ldg(wp + j);
                        }
                    }
                    fire = (pot > 15.f) ? 1 : 0;
                }
                pooled |= fire;
            }
        if (pooled) poolbase[(size_t)f * HPD * HPD] = 1;
        pcv += pooled;
    }
    g_pc[(t * HPD + py + 1) * HPD + px + 1] = (uint8_t)pcv;
}

// ---------------- K B1: classify (t,pixel) full vs deficient ----------------
__global__ void kB1() {
    int i = blockIdx.x * 256 + threadIdx.x;
    if (i >= TT * NPIX) return;
    int t = i / NPIX, pix = i % NPIX;
    int y = pix / HP, x = pix % HP;
    int s = 0;
#pragma unroll
    for (int dy = 0; dy < 3; dy++)
#pragma unroll
        for (int dx = 0; dx < 3; dx++)
            s += g_pc[(t * HPD + y + dy) * HPD + x + dx];
    if (s == TAPS) {
        g_maxv[i] = g_iMaxv; g_maxi[i] = g_iMaxi;
    } else {
        int slot = atomicAdd(&g_count, 1);
        g_list[slot] = i;
    }
}

// ---------------- K B2: deficient (t,pixel): all-250 pot2 + first-argmax ----------------
__global__ void __launch_bounds__(256) kB2() {
    __shared__ uint32_t pmask[9];
    __shared__ float rv[256];
    __shared__ int   ri[256];
    int cnt = g_count;
    int f = threadIdx.x;
    for (int e = blockIdx.x; e < cnt; e += gridDim.x) {
        int id = g_list[e];
        int t = id / NPIX, pix = id % NPIX;
        int y = pix / HP, x = pix % HP;
        if (f < 9) {
            int yy = y + f / 3, xx = x + f % 3;
            uint32_t m = 0;
            const uint8_t* pb = &g_pool[((size_t)t * F1) * HPD * HPD + (size_t)yy * HPD + xx];
            for (int c = 0; c < F1; c++) m |= ((uint32_t)pb[(size_t)c * HPD * HPD]) << c;
            pmask[f] = m;
        }
        __syncthreads();
        float pot = g_S[f];
#pragma unroll
        for (int p = 0; p < 9; p++) {
            uint32_t mm = (~pmask[p]) & 0x3FFFFFFFu;
            while (mm) {
                int c = __ffs(mm) - 1; mm &= mm - 1;
                pot -= g_w2t[(c * 9 + p) * 256 + f];
            }
        }
        float pf = (f < F2 && pot > 10.f) ? pot : 0.f;
        rv[f] = pf; ri[f] = f;
        __syncthreads();
        for (int st = 128; st >= 1; st >>= 1) {
            if (f < st) {
                float o = rv[f + st]; int oi = ri[f + st];
                if (o > rv[f] || (o == rv[f] && oi < ri[f])) { rv[f] = o; ri[f] = oi; }
            }
            __syncthreads();
        }
        if (f == 0) { g_maxv[id] = rv[0]; g_maxi[id] = ri[0]; }
        __syncthreads();
    }
}

// ---------------- K B3: per-pixel earliest / winner feature / fired_last ----------------
__global__ void kB3() {
    int pix = blockIdx.x * 256 + threadIdx.x;
    if (pix >= NPIX) return;
    int cntf = 0, lastc = 0;
    for (int t = 0; t < TT; t++) {
        int c = (g_maxv[t * NPIX + pix] > 0.f) ? 1 : 0;
        cntf += c;
        if (t == TT - 1) lastc = c;
    }
    int e = TT - cntf; e = e < 0 ? 0 : (e > TT - 1 ? TT - 1 : e);
    g_win[pix] = g_maxi[e * NPIX + pix];
    g_fired[pix] = (uint8_t)lastc;
}

// ---------------- K B4: pot value of winning channel per (t,pixel) ----------------
__global__ void kB4() {
    int i = blockIdx.x * 256 + threadIdx.x;
    if (i >= TT * NPIX) return;
    int t = i / NPIX, pix = i % NPIX;
    float pv = 0.f;
    if (g_fired[pix]) {
        int win = g_win[pix];
        int y = pix / HP, x = pix % HP;
        int s = 0;
#pragma unroll
        for (int dy = 0; dy < 3; dy++)
#pragma unroll
            for (int dx = 0; dx < 3; dx++)
                s += g_pc[(t * HPD + y + dy) * HPD + x + dx];
        float pot = g_S[win];
        if (s != TAPS) {
            for (int p = 0; p < 9; p++) {
                int yy = y + p / 3, xx = x + p % 3;
                const uint8_t* pb = &g_pool[((size_t)t * F1) * HPD * HPD + (size_t)yy * HPD + xx];
                for (int c = 0; c < F1; c++)
                    if (!pb[(size_t)c * HPD * HPD]) pot -= g_w2t[(c * 9 + p) * 256 + win];
            }
        }
        pv = (pot > 10.f) ? pot : 0.f;
    }
    g_pv[i] = pv;
}

// ---------------- K B5a: nspk / val / global max firing value ----------------
__global__ void kB5a() {
    int pix = blockIdx.x * 256 + threadIdx.x;
    if (pix >= NPIX) return;
    int ns = 0;
    for (int t = 0; t < TT; t++) ns += (g_pv[t * NPIX + pix] > 0.f) ? 1 : 0;
    int e = TT - ns; e = e < 0 ? 0 : (e > TT - 1 ? TT - 1 : e);
    float val = g_pv[e * NPIX + pix];
    g_val[pix] = val;
    if (ns > 0) atomicMax(&g_vmaxbits, __float_as_int(val));
}

// ---------------- K B5b: per-pixel total (sequential add to match jnp.sum) ----------------
__global__ void kB5b() {
    int pix = blockIdx.x * 256 + threadIdx.x;
    if (pix >= NPIX) return;
    float v = __int_as_float(g_vmaxbits) * 15.0f;
    float w = g_val[pix] + v;
    float tot = 0.f;
    for (int t = 0; t < TT; t++)
        if (g_pv[t * NPIX + pix] > 0.f) tot += w;
    g_total[pix] = tot;
}

// ---------------- K B7: scatter nonzero spk/pot into dense output ----------------
__global__ void kB7(float* __restrict__ out) {
    int i = blockIdx.x * 256 + threadIdx.x;
    if (i >= TT * NPIX) return;
    int t = i / NPIX, pix = i % NPIX;
    float pv = g_pv[i];
    if (pv > 0.f) {
        int win = g_win[pix];
        size_t idx = ((size_t)(t * F2 + win)) * NPIX + pix;
        out[idx] = 1.0f;
        out[POT_OFF + idx] = pv;
    }
}

// ---------------- K B6: k-winners (single block, register-light, exact argmax tie-break) ----------------
__global__ void __launch_bounds__(1024) kB6(float* __restrict__ outw) {
    __shared__ unsigned long long red[1024];
    __shared__ int winfo[3];
    int tid = threadIdx.x;
    unsigned kill = 0;   // 16-bit per-thread kill mask (e = tid*16 + k)
    for (int r = 0; r < 8; r++) {
        unsigned long long best = 0;
        for (int k = 0; k < 16; k++) {
            int e = tid * 16 + k;
            if (e < NPIX && !((kill >> k) & 1u)) {
                float tv = g_total[e];
                if (tv > 0.f) {
                    unsigned flat = (unsigned)(g_win[e] * NPIX + e);
                    unsigned long long key =
                        ((unsigned long long)__float_as_uint(tv) << 32) | (0xFFFFFFFFu - flat);
                    if (key > best) best = key;
                }
            }
        }
        red[tid] = best;
        __syncthreads();
        for (int st = 512; st >= 1; st >>= 1) {
            if (tid < st) {
                unsigned long long o = red[tid + st];
                if (o > red[tid]) red[tid] = o;
            }
            __syncthreads();
        }
        if (tid == 0) {
            unsigned long long b = red[0];
            if (b == 0) {
                winfo[0] = -1;
                outw[r * 3] = -1.f; outw[r * 3 + 1] = -1.f; outw[r * 3 + 2] = -1.f;
            } else {
                unsigned flat = 0xFFFFFFFFu - (unsigned)(b & 0xFFFFFFFFu);
                int c = flat / NPIX, pix = flat % NPIX;
                winfo[0] = c; winfo[1] = pix / HP; winfo[2] = pix % HP;
                outw[r * 3] = (float)c;
                outw[r * 3 + 1] = (float)winfo[1];
                outw[r * 3 + 2] = (float)winfo[2];
            }
        }
        __syncthreads();
        int wc = winfo[0];
        if (wc >= 0) {
            int wy = winfo[1], wx = winfo[2];
            for (int k = 0; k < 16; k++) {
                int e = tid * 16 + k;
                if (e < NPIX) {
                    int y = e / HP, x = e % HP;
                    if (g_win[e] == wc || (abs(y - wy) <= 1 && abs(x - wx) <= 1))
                        kill |= (1u << k);
                }
            }
        }
        __syncthreads();
    }
}

// ---------------- host launcher ----------------
extern "C" void kernel_launch(void* const* d_in, const int* in_sizes, int n_in,
                              void* d_out, int out_size) {
    const int*   inp = (const int*)d_in[0];
    // d_in[1] = max_layer (unused, == 2)
    const float* w1  = (const float*)d_in[2];
    const float* w2  = (const float*)d_in[3];
    float* out = (float*)d_out;

    cudaMemsetAsync(d_out, 0, (size_t)out_size * sizeof(float), 0);

    k_zero <<<1800, 256>>>();
    k_wprep<<<1, 32>>>(w1);
    k_w2t  <<<TAPS, 256>>>(w2);
    k_prep <<<1, 256>>>(w2);

    kA1<<<TT * 256, 256>>>(inp);
    dim3 gA2(4, 32, TT), bA2(32, 4);
    kA2<<<gA2, bA2>>>(w1);

    kB1<<<(TT * NPIX + 255) / 256, 256>>>();
    kB2<<<4096, 256>>>();
    kB3<<<(NPIX + 255) / 256, 256>>>();
    kB4<<<(TT * NPIX + 255) / 256, 256>>>();
    kB5a<<<(NPIX + 255) / 256, 256>>>();
    kB5b<<<(NPIX + 255) / 256, 256>>>();
    kB7<<<(TT * NPIX + 255) / 256, 256>>>(out);
    kB6<<<1, 1024>>>(out + WIN_OFF);
}